// round 12
// baseline (speedup 1.0000x reference)
#include <cuda_runtime.h>
#include <cuda_bf16.h>
#include <cuda_fp16.h>
#include <stdint.h>
#include <math.h>

#define BATCH 8
#define LSEQ  2048
#define DDIM  1024

typedef __nv_bfloat16 bf16;

// ---------------------------------------------------------------------------
// Scratch (device globals: no allocation allowed)
// ---------------------------------------------------------------------------
__device__ float  g_scores[(size_t)BATCH * LSEQ * LSEQ];           // 134 MB
__device__ bf16   g_xh [(size_t)BATCH * LSEQ * DDIM];
__device__ bf16   g_xl [(size_t)BATCH * LSEQ * DDIM];
__device__ __half g_xth[(size_t)BATCH * DDIM * LSEQ];              // x^T fp16 hi
__device__ bf16   g_wh [(size_t)DDIM * DDIM];
__device__ bf16   g_wl [(size_t)DDIM * DDIM];
__device__ bf16   g_ph [(size_t)BATCH * LSEQ * DDIM];
__device__ bf16   g_pl [(size_t)BATCH * LSEQ * DDIM];
__device__ __half g_ah [(size_t)BATCH * LSEQ * LSEQ];              // alpha fp16

// ---------------------------------------------------------------------------
// PTX helpers (base sm_103 target — NO tcgen05)
// ---------------------------------------------------------------------------
__device__ __forceinline__ uint32_t smem_u32(const void* p) {
    uint32_t a;
    asm("{ .reg .u64 t; cvta.to.shared.u64 t, %1; cvt.u32.u64 %0, t; }" : "=r"(a) : "l"(p));
    return a;
}

__device__ __forceinline__ void cpa16(uint32_t d, const void* s) {
    asm volatile("cp.async.cg.shared.global [%0], [%1], 16;" :: "r"(d), "l"(s) : "memory");
}

#define CP_COMMIT() asm volatile("cp.async.commit_group;" ::: "memory")
#define CP_WAIT1()  asm volatile("cp.async.wait_group 1;" ::: "memory")

#define LDSM4(r, addr) \
    asm volatile("ldmatrix.sync.aligned.m8n8.x4.shared.b16 {%0,%1,%2,%3}, [%4];" \
        : "=r"((r)[0]), "=r"((r)[1]), "=r"((r)[2]), "=r"((r)[3]) : "r"(addr))

#define MMA(d, a, b0, b1) \
    asm volatile("mma.sync.aligned.m16n8k16.row.col.f32.bf16.bf16.f32 " \
        "{%0,%1,%2,%3}, {%4,%5,%6,%7}, {%8,%9}, {%0,%1,%2,%3};" \
        : "+f"((d)[0]), "+f"((d)[1]), "+f"((d)[2]), "+f"((d)[3]) \
        : "r"((a)[0]), "r"((a)[1]), "r"((a)[2]), "r"((a)[3]), "r"(b0), "r"(b1))

#define MMAH(d, a, b0, b1) \
    asm volatile("mma.sync.aligned.m16n8k16.row.col.f32.f16.f16.f32 " \
        "{%0,%1,%2,%3}, {%4,%5,%6,%7}, {%8,%9}, {%0,%1,%2,%3};" \
        : "+f"((d)[0]), "+f"((d)[1]), "+f"((d)[2]), "+f"((d)[3]) \
        : "r"((a)[0]), "r"((a)[1]), "r"((a)[2]), "r"((a)[3]), "r"(b0), "r"(b1))

// ---------------------------------------------------------------------------
// 3-pass bf16 GEMM core (proj/scores): C(128x128) = (Ah+Al)(Bh+Bl)^T
// Stage = K=64 (64KB): A panels +0,+16384; B panels +32768,+49152.
// Panel row = 128B [hi 32k | lo 32k], XOR swizzle. 3 stages (192KB).
// 512 threads, 16 warps (4x4), warp tile 32x32. Frags double-buffered.
// TWO output tiles per CTA: stage counter s = 0..31 spans both tiles, so
// tile1's first stages load during tile0's mainloop tail and its epilogue.
// ---------------------------------------------------------------------------
#define NTH 512
#define STG    65536
#define NSTAGES_TOT 32                      // 2 tiles x 16 stages (K=1024)
// scores epilogue staging lives beyond the 3 stage buffers
#define EPI_OFF   (3 * STG)                 // 196608
#define SMEM_PROJ (3 * STG)
#define SMEM_SC   (3 * STG + 128 * 33 * 4 + 1024)   // 214528

struct Frag {
    uint32_t aH[2][4], aL[2][4], bH[2][4], bL[2][4];
};

__device__ __forceinline__ void issue_stage(uint32_t sb, int s, int tid,
    const bf16* __restrict__ Ah, const bf16* __restrict__ Al, size_t lda,
    const bf16* __restrict__ Bh, const bf16* __restrict__ Bl, size_t ldb, int kc)
{
    const uint32_t base = sb + (uint32_t)(s % 3) * STG;
    #pragma unroll
    for (int panel = 0; panel < 2; panel++) {
        const int kcp = kc + panel * 32;
        const uint32_t pb = base + (uint32_t)panel * 16384;
        #pragma unroll
        for (int j = 0; j < 2; j++) {
            const int q   = tid + j * NTH;       // 0..1023
            const int row = q >> 3;
            const int c   = q & 7;               // 0-3 hi, 4-7 lo
            const uint32_t off = (uint32_t)(row * 128) + ((uint32_t)(c ^ (row & 7)) << 4);
            const bf16* sa = (c < 4) ? Ah + (size_t)row * lda + kcp + c * 8
                                     : Al + (size_t)row * lda + kcp + (c - 4) * 8;
            const bf16* sbp = (c < 4) ? Bh + (size_t)row * ldb + kcp + c * 8
                                      : Bl + (size_t)row * ldb + kcp + (c - 4) * 8;
            cpa16(pb + off, sa);
            cpa16(pb + 32768 + off, sbp);
        }
    }
    CP_COMMIT();
}

__device__ __forceinline__ void load_frags(uint32_t stage, int kk, int m0, int n0,
                                           int lane, Frag& f)
{
    const uint32_t base = stage + (uint32_t)(kk >> 1) * 16384;
    const int cb = (kk & 1) * 2;
    const int rA = lane & 15, cA = lane >> 4;
    const int rB = (lane & 7) + ((lane >> 4) << 3), cB = (lane >> 3) & 1;
    #pragma unroll
    for (int mt = 0; mt < 2; mt++) {
        const uint32_t rowb = base + (uint32_t)((m0 + mt * 16 + rA) * 128);
        LDSM4(f.aH[mt], rowb + ((uint32_t)((cb + cA)     ^ (rA & 7)) << 4));
        LDSM4(f.aL[mt], rowb + ((uint32_t)((cb + 4 + cA) ^ (rA & 7)) << 4));
    }
    #pragma unroll
    for (int nt2 = 0; nt2 < 2; nt2++) {
        const uint32_t rowb = base + 32768 + (uint32_t)((n0 + nt2 * 16 + rB) * 128);
        LDSM4(f.bH[nt2], rowb + ((uint32_t)((cb + cB)     ^ (rB & 7)) << 4));
        LDSM4(f.bL[nt2], rowb + ((uint32_t)((cb + 4 + cB) ^ (rB & 7)) << 4));
    }
}

__device__ __forceinline__ void do_mmas(const Frag& f, float acc[2][4][4]) {
    #pragma unroll
    for (int mt = 0; mt < 2; mt++)
        #pragma unroll
        for (int nt = 0; nt < 4; nt++) {
            const int g = nt >> 1, o = (nt & 1) * 2;
            MMA(acc[mt][nt], f.aH[mt], f.bH[g][o], f.bH[g][o + 1]);
        }
    #pragma unroll
    for (int mt = 0; mt < 2; mt++)
        #pragma unroll
        for (int nt = 0; nt < 4; nt++) {
            const int g = nt >> 1, o = (nt & 1) * 2;
            MMA(acc[mt][nt], f.aH[mt], f.bL[g][o], f.bL[g][o + 1]);
        }
    #pragma unroll
    for (int mt = 0; mt < 2; mt++)
        #pragma unroll
        for (int nt = 0; nt < 4; nt++) {
            const int g = nt >> 1, o = (nt & 1) * 2;
            MMA(acc[mt][nt], f.aL[mt], f.bH[g][o], f.bH[g][o + 1]);
        }
}

// Two-tile mainloop: 32 stages, epilogue fired after stages 15 and 31.
template <typename FIssue, typename FEpi>
__device__ __forceinline__ void run_gemm2(uint32_t sb, int tid,
                                          FIssue issue, FEpi epi)
{
    float acc[2][4][4];
    #pragma unroll
    for (int mt = 0; mt < 2; mt++)
        #pragma unroll
        for (int nt = 0; nt < 4; nt++)
            #pragma unroll
            for (int i = 0; i < 4; i++) acc[mt][nt][i] = 0.f;

    issue(0);
    issue(1);

    const int wid = tid >> 5, lane = tid & 31;
    const int m0 = (wid & 3) * 32, n0 = (wid >> 2) * 32;

    CP_WAIT1();
    __syncthreads();

    Frag fa, fb;
    load_frags(sb, 0, m0, n0, lane, fa);

    for (int s = 0; s < NSTAGES_TOT; s++) {
        const uint32_t cur = sb + (uint32_t)(s % 3) * STG;
        if (s + 2 < NSTAGES_TOT) issue(s + 2); else CP_COMMIT();

        load_frags(cur, 1, m0, n0, lane, fb);
        do_mmas(fa, acc);
        load_frags(cur, 2, m0, n0, lane, fa);
        do_mmas(fb, acc);
        load_frags(cur, 3, m0, n0, lane, fb);
        do_mmas(fa, acc);

        CP_WAIT1();
        __syncthreads();

        const int ps = (s + 1 < NSTAGES_TOT) ? s + 1 : s;
        load_frags(sb + (uint32_t)(ps % 3) * STG, 0, m0, n0, lane, fa);
        do_mmas(fb, acc);

        if ((s & 15) == 15) {
            epi(s >> 4, acc);
            #pragma unroll
            for (int mt = 0; mt < 2; mt++)
                #pragma unroll
                for (int nt = 0; nt < 4; nt++)
                    #pragma unroll
                    for (int i = 0; i < 4; i++) acc[mt][nt][i] = 0.f;
        }
    }
}

// ---------------------------------------------------------------------------
// 1-pass fp16 GEMM core (av): C(128x128) = Ah @ Bh^T.  (unchanged from R11)
// 256 threads, warp 64x32, K=64 stages x3 (96KB) -> 2 CTAs/SM, frag dbl-buf.
// ---------------------------------------------------------------------------
#define NTH_AV 256
#define STG_AV 32768
#define SMEM_AV (3 * STG_AV)

struct FragAv {
    uint32_t aH[4][4], bH[2][4];
};

__device__ __forceinline__ void issue_stage_av(uint32_t sb, int s, int tid,
    const __half* __restrict__ Ah, size_t lda,
    const __half* __restrict__ Bh, size_t ldb, int kc)
{
    const uint32_t base = sb + (uint32_t)(s % 3) * STG_AV;
    #pragma unroll
    for (int j = 0; j < 4; j++) {
        const int q   = tid + j * NTH_AV;
        const int row = q >> 3;
        const int c   = q & 7;
        const uint32_t off = (uint32_t)(row * 128) + ((uint32_t)(c ^ (row & 7)) << 4);
        cpa16(base + off, Ah + (size_t)row * lda + kc + c * 8);
    }
    #pragma unroll
    for (int j = 0; j < 4; j++) {
        const int q   = tid + j * NTH_AV;
        const int row = q >> 3;
        const int c   = q & 7;
        const uint32_t off = 16384u + (uint32_t)(row * 128)
                           + ((uint32_t)(c ^ (row & 7)) << 4);
        cpa16(base + off, Bh + (size_t)row * ldb + kc + c * 8);
    }
    CP_COMMIT();
}

__device__ __forceinline__ void load_frags_av(uint32_t stage, int kk, int m0, int n0,
                                              int lane, FragAv& f)
{
    const int cb = kk * 2;
    const int rA = lane & 15, cA = lane >> 4;
    const int rB = (lane & 7) + ((lane >> 4) << 3), cB = (lane >> 3) & 1;
    #pragma unroll
    for (int mt = 0; mt < 4; mt++) {
        const uint32_t rowb = stage + (uint32_t)((m0 + mt * 16 + rA) * 128);
        LDSM4(f.aH[mt], rowb + ((uint32_t)((cb + cA) ^ (rA & 7)) << 4));
    }
    #pragma unroll
    for (int nt2 = 0; nt2 < 2; nt2++) {
        const uint32_t rowb = stage + 16384 + (uint32_t)((n0 + nt2 * 16 + rB) * 128);
        LDSM4(f.bH[nt2], rowb + ((uint32_t)((cb + cB) ^ (rB & 7)) << 4));
    }
}

__device__ __forceinline__ void do_mmas_av(const FragAv& f, float acc[4][4][4]) {
    #pragma unroll
    for (int mt = 0; mt < 4; mt++)
        #pragma unroll
        for (int nt = 0; nt < 4; nt++) {
            const int g = nt >> 1, o = (nt & 1) * 2;
            MMAH(acc[mt][nt], f.aH[mt], f.bH[g][o], f.bH[g][o + 1]);
        }
}

__device__ __forceinline__ void run_gemm_av(uint32_t sb, int tid,
    const __half* __restrict__ Ah, size_t lda,
    const __half* __restrict__ Bh, size_t ldb, int nk,
    float acc[4][4][4])
{
    #pragma unroll
    for (int mt = 0; mt < 4; mt++)
        #pragma unroll
        for (int nt = 0; nt < 4; nt++)
            #pragma unroll
            for (int i = 0; i < 4; i++) acc[mt][nt][i] = 0.f;

    issue_stage_av(sb, 0, tid, Ah, lda, Bh, ldb, 0);
    issue_stage_av(sb, 1, tid, Ah, lda, Bh, ldb, 64);

    const int wid = tid >> 5, lane = tid & 31;
    const int m0 = (wid & 1) * 64, n0 = (wid >> 1) * 32;

    CP_WAIT1();
    __syncthreads();

    FragAv fa, fb;
    load_frags_av(sb, 0, m0, n0, lane, fa);

    for (int kt = 0; kt < nk; kt++) {
        const uint32_t cur = sb + (uint32_t)(kt % 3) * STG_AV;
        if (kt + 2 < nk)
            issue_stage_av(sb, kt + 2, tid, Ah, lda, Bh, ldb, (kt + 2) * 64);
        else
            CP_COMMIT();

        load_frags_av(cur, 1, m0, n0, lane, fb);
        do_mmas_av(fa, acc);
        load_frags_av(cur, 2, m0, n0, lane, fa);
        do_mmas_av(fb, acc);
        load_frags_av(cur, 3, m0, n0, lane, fb);
        do_mmas_av(fa, acc);

        CP_WAIT1();
        __syncthreads();

        const int pkt = (kt + 1 < nk) ? kt + 1 : kt;
        load_frags_av(sb + (uint32_t)(pkt % 3) * STG_AV, 0, m0, n0, lane, fa);
        do_mmas_av(fb, acc);
    }
}

__device__ __forceinline__ uint32_t packbf(float a, float b) {
    __nv_bfloat162 t = __floats2bfloat162_rn(a, b);
    return *reinterpret_cast<uint32_t*>(&t);
}
__device__ __forceinline__ uint32_t packh(float a, float b) {
    __half2 t = __floats2half2_rn(a, b);
    return *reinterpret_cast<uint32_t*>(&t);
}

// ---------------------------------------------------------------------------
// GEMM 1: proj = relu(x @ W^T + b) -> split bf16. Two n-tiles per CTA.
// ---------------------------------------------------------------------------
__global__ __launch_bounds__(NTH, 1) void proj_gemm(const float* __restrict__ bias) {
    extern __shared__ char smem[];
    const uint32_t sb = smem_u32(smem);
    const int tid = threadIdx.x;
    const int mblk = blockIdx.y * 128;
    const int nb0  = blockIdx.x * 256;          // tiles at nb0, nb0+128

    const uint32_t aoff = (uint32_t)mblk * DDIM;
    const uint32_t ob0  = (uint32_t)nb0 * DDIM;
    const uint32_t ob1  = ob0 + 128u * DDIM;

    auto issue = [&](int s) {
        const uint32_t ob = (s < 16) ? ob0 : ob1;
        issue_stage(sb, s, tid, g_xh + aoff, g_xl + aoff, DDIM,
                    g_wh + ob, g_wl + ob, DDIM, (s & 15) * 64);
    };

    auto epi = [&](int t, float (&acc)[2][4][4]) {
        const int nblk = nb0 + t * 128;
        const int wid = tid >> 5, lane = tid & 31;
        const int m0 = (wid & 3) * 32, n0 = (wid >> 2) * 32;
        const int quad = lane >> 2, tq = lane & 3;
        #pragma unroll
        for (int mt = 0; mt < 2; mt++)
            #pragma unroll
            for (int nt = 0; nt < 4; nt++) {
                const int col = nblk + n0 + nt * 8 + tq * 2;
                const float b0 = bias[col], b1 = bias[col + 1];
                #pragma unroll
                for (int h = 0; h < 2; h++) {
                    const int row = mblk + m0 + mt * 16 + quad + h * 8;
                    float v0 = fmaxf(acc[mt][nt][h * 2 + 0] + b0, 0.f);
                    float v1 = fmaxf(acc[mt][nt][h * 2 + 1] + b1, 0.f);
                    bf16 h0 = __float2bfloat16(v0), h1 = __float2bfloat16(v1);
                    float l0 = v0 - __bfloat162float(h0);
                    float l1 = v1 - __bfloat162float(h1);
                    *reinterpret_cast<uint32_t*>(g_ph + (size_t)row * DDIM + col) =
                        packbf(__bfloat162float(h0), __bfloat162float(h1));
                    *reinterpret_cast<uint32_t*>(g_pl + (size_t)row * DDIM + col) =
                        packbf(l0, l1);
                }
            }
    };

    run_gemm2(sb, tid, issue, epi);
}

// ---------------------------------------------------------------------------
// GEMM 2 (symmetric, two pairs per CTA): each tile = pair (ti,tj), ti<=tj.
// Writes tile + mirror via quarter-tile smem staging in the EPI region
// (separate from stage buffers so next-tile loads stay live).
// ---------------------------------------------------------------------------
__global__ __launch_bounds__(NTH, 1) void scores_gemm(const int* __restrict__ x_mask) {
    extern __shared__ char smem[];
    const uint32_t sb = smem_u32(smem);
    const int tid = threadIdx.x;
    const int b = blockIdx.y;

    int p = blockIdx.x * 2;
    int ti0 = 0;
    while (p >= 16 - ti0) { p -= 16 - ti0; ti0++; }
    const int tj0 = ti0 + p;
    const int ti1 = (tj0 < 15) ? ti0 : ti0 + 1;
    const int tj1 = (tj0 < 15) ? tj0 + 1 : ti1;

    const uint32_t pb = (uint32_t)b * (LSEQ * DDIM);
    const uint32_t oA0 = pb + (uint32_t)ti0 * 128 * DDIM;
    const uint32_t oB0 = pb + (uint32_t)tj0 * 128 * DDIM;
    const uint32_t oA1 = pb + (uint32_t)ti1 * 128 * DDIM;
    const uint32_t oB1 = pb + (uint32_t)tj1 * 128 * DDIM;

    auto issue = [&](int s) {
        const uint32_t oA = (s < 16) ? oA0 : oA1;
        const uint32_t oB = (s < 16) ? oB0 : oB1;
        issue_stage(sb, s, tid, g_ph + oA, g_pl + oA, DDIM,
                    g_ph + oB, g_pl + oB, DDIM, (s & 15) * 64);
    };

    const int* mk = x_mask + (size_t)b * LSEQ;
    float* S = g_scores + (size_t)b * LSEQ * LSEQ;

    auto epi = [&](int t, float (&acc)[2][4][4]) {
        const int ti = t ? ti1 : ti0;
        const int tj = t ? tj1 : tj0;
        float (*sE)[33] = reinterpret_cast<float(*)[33]>(smem + EPI_OFF);
        int* smi = reinterpret_cast<int*>(smem + EPI_OFF + 128 * 33 * 4);
        int* smj = smi + 128;

        const int wid = tid >> 5, lane = tid & 31;
        const int m0 = (wid & 3) * 32;
        const int wg = wid >> 2;                 // n-quarter owned by this warp
        const int quad = lane >> 2, tq = lane & 3;
        const float NEGINF = -INFINITY;

        if (tid < 128) { smi[tid] = mk[ti * 128 + tid]; smj[tid] = mk[tj * 128 + tid]; }

        #pragma unroll
        for (int q = 0; q < 4; q++) {
            __syncthreads();
            if (wg == q) {
                #pragma unroll
                for (int mt = 0; mt < 2; mt++)
                    #pragma unroll
                    for (int nt = 0; nt < 4; nt++) {
                        const int c = nt * 8 + tq * 2;       // local col in quarter
                        #pragma unroll
                        for (int h = 0; h < 2; h++) {
                            const int r = m0 + mt * 16 + quad + h * 8;
                            sE[r][c]     = acc[mt][nt][h * 2 + 0];
                            sE[r][c + 1] = acc[mt][nt][h * 2 + 1];
                        }
                    }
            }
            __syncthreads();

            // normal region: rows ti*128+r, cols tj*128 + q*32 + c
            {
                const int r  = tid & 127;
                const int c0 = (tid >> 7) * 8;               // 4 groups x 8 cols
                float* Srow = S + (size_t)(ti * 128 + r) * LSEQ + tj * 128 + q * 32;
                #pragma unroll
                for (int cc = 0; cc < 8; cc += 4) {
                    const int c = c0 + cc;
                    const int cg = q * 32 + c;               // tile-local col
                    float x0 = sE[r][c],     x1 = sE[r][c + 1];
                    float x2 = sE[r][c + 2], x3 = sE[r][c + 3];
                    if (ti == tj) {
                        if (r == cg)     x0 = 0.f;
                        if (r == cg + 1) x1 = 0.f;
                        if (r == cg + 2) x2 = 0.f;
                        if (r == cg + 3) x3 = 0.f;
                    }
                    float4 v;
                    v.x = smj[cg]     ? NEGINF : x0;
                    v.y = smj[cg + 1] ? NEGINF : x1;
                    v.z = smj[cg + 2] ? NEGINF : x2;
                    v.w = smj[cg + 3] ? NEGINF : x3;
                    *reinterpret_cast<float4*>(Srow + c) = v;
                }
            }
            // mirror region (ti != tj): rows tj*128 + q*32 + rr, cols ti*128 + cb
            if (ti != tj) {
                const int rr = tid & 31;
                const int cb = (tid >> 5) * 8;               // 16 groups x 8 cols
                float* Mrow = S + (size_t)(tj * 128 + q * 32 + rr) * LSEQ + ti * 128;
                #pragma unroll
                for (int cc = 0; cc < 8; cc += 4) {
                    const int c = cb + cc;
                    float4 v;
                    v.x = smi[c]     ? NEGINF : sE[c][rr];
                    v.y = smi[c + 1] ? NEGINF : sE[c + 1][rr];
                    v.z = smi[c + 2] ? NEGINF : sE[c + 2][rr];
                    v.w = smi[c + 3] ? NEGINF : sE[c + 3][rr];
                    *reinterpret_cast<float4*>(Mrow + c) = v;
                }
            }
        }
        __syncthreads();
    };

    run_gemm2(sb, tid, issue, epi);
}

// ---------------------------------------------------------------------------
// GEMM 3: out = alpha @ x   (fp16 1-pass, CTA 128x128, warp 64x32, 2 CTA/SM)
// ---------------------------------------------------------------------------
__global__ __launch_bounds__(NTH_AV, 2) void av_gemm(float* __restrict__ out) {
    extern __shared__ char smem[];
    const uint32_t sb = smem_u32(smem);
    const int tid = threadIdx.x;
    const int b = blockIdx.z;
    const int mblk = blockIdx.y * 128, nblk = blockIdx.x * 128;

    float acc[4][4][4];
    run_gemm_av(sb, tid,
                g_ah + ((size_t)b * LSEQ + mblk) * LSEQ, LSEQ,
                g_xth + ((size_t)b * DDIM + nblk) * LSEQ, LSEQ,
                LSEQ / 64, acc);

    const int wid = tid >> 5, lane = tid & 31;
    const int m0 = (wid & 1) * 64, n0 = (wid >> 1) * 32;
    const int quad = lane >> 2, tq = lane & 3;

    #pragma unroll
    for (int mt = 0; mt < 4; mt++)
        #pragma unroll
        for (int nt = 0; nt < 4; nt++) {
            const int col = nblk + n0 + nt * 8 + tq * 2;
            #pragma unroll
            for (int h = 0; h < 2; h++) {
                const int row = mblk + m0 + mt * 16 + quad + h * 8;
                float2 o;
                o.x = acc[mt][nt][h * 2 + 0];
                o.y = acc[mt][nt][h * 2 + 1];
                *reinterpret_cast<float2*>(out + ((size_t)b * LSEQ + row) * DDIM + col) = o;
            }
        }
}

// ---------------------------------------------------------------------------
// Softmax over keys (fp32 scores in, fp16 alpha out, MUFU exp)
// ---------------------------------------------------------------------------
__global__ __launch_bounds__(256) void softmax_kernel() {
    const size_t row = blockIdx.x;
    const float* p = g_scores + row * LSEQ;
    const int t = threadIdx.x;

    float4 v0 = reinterpret_cast<const float4*>(p)[t * 2];
    float4 v1 = reinterpret_cast<const float4*>(p)[t * 2 + 1];

    float m = fmaxf(fmaxf(fmaxf(v0.x, v0.y), fmaxf(v0.z, v0.w)),
                    fmaxf(fmaxf(v1.x, v1.y), fmaxf(v1.z, v1.w)));

    __shared__ float red[8];
    #pragma unroll
    for (int off = 16; off > 0; off >>= 1)
        m = fmaxf(m, __shfl_xor_sync(0xffffffffu, m, off));
    if ((t & 31) == 0) red[t >> 5] = m;
    __syncthreads();
    if (t == 0) {
        float mm = red[0];
        #pragma unroll
        for (int w = 1; w < 8; w++) mm = fmaxf(mm, red[w]);
        red[0] = mm;
    }
    __syncthreads();
    m = red[0];
    __syncthreads();

    float e[8];
    e[0] = __expf(v0.x - m); e[1] = __expf(v0.y - m);
    e[2] = __expf(v0.z - m); e[3] = __expf(v0.w - m);
    e[4] = __expf(v1.x - m); e[5] = __expf(v1.y - m);
    e[6] = __expf(v1.z - m); e[7] = __expf(v1.w - m);
    float s = e[0] + e[1] + e[2] + e[3] + e[4] + e[5] + e[6] + e[7];
    #pragma unroll
    for (int off = 16; off > 0; off >>= 1)
        s += __shfl_xor_sync(0xffffffffu, s, off);
    if ((t & 31) == 0) red[t >> 5] = s;
    __syncthreads();
    if (t == 0) {
        float ss = 0.f;
        #pragma unroll
        for (int w = 0; w < 8; w++) ss += red[w];
        red[0] = ss;
    }
    __syncthreads();
    const float inv = 1.0f / red[0];

    uint32_t hh[4];
    #pragma unroll
    for (int i = 0; i < 4; i++)
        hh[i] = packh(e[2 * i] * inv, e[2 * i + 1] * inv);
    *reinterpret_cast<uint4*>(g_ah + row * LSEQ + t * 8) = *reinterpret_cast<uint4*>(hh);
}

// ---------------------------------------------------------------------------
// Fused x prep: read x once -> xh/xl (row-major bf16) + xth (fp16 transposed)
// ---------------------------------------------------------------------------
__global__ __launch_bounds__(256) void prep_x_kernel(const float* __restrict__ x) {
    __shared__ float t[32][33];
    const int b = blockIdx.z, d0 = blockIdx.x * 32, l0 = blockIdx.y * 32;
    const int tx = threadIdx.x & 31, ty = threadIdx.x >> 5;   // 32 x 8
    const float* xb = x + (size_t)b * LSEQ * DDIM;
    bf16* xh = g_xh + (size_t)b * LSEQ * DDIM;
    bf16* xl = g_xl + (size_t)b * LSEQ * DDIM;

    #pragma unroll
    for (int j = 0; j < 4; j++) {
        const int l = l0 + ty + j * 8;
        const float v = xb[(size_t)l * DDIM + d0 + tx];
        t[ty + j * 8][tx] = v;
        bf16 h = __float2bfloat16(v);
        xh[(size_t)l * DDIM + d0 + tx] = h;
        xl[(size_t)l * DDIM + d0 + tx] = __float2bfloat16(v - __bfloat162float(h));
    }
    __syncthreads();
    __half* oh = g_xth + (size_t)b * DDIM * LSEQ;
    #pragma unroll
    for (int j = 0; j < 4; j++) {
        float v = t[tx][ty + j * 8];
        oh[(size_t)(d0 + ty + j * 8) * LSEQ + l0 + tx] = __float2half_rn(v);
    }
}

// fp32 -> split-bf16 conversion (W)
__global__ __launch_bounds__(256) void split_kernel(const float* __restrict__ s,
                                                    bf16* __restrict__ hi,
                                                    bf16* __restrict__ lo, int n4) {
    const int i = blockIdx.x * 256 + threadIdx.x;
    if (i >= n4) return;
    float4 v = reinterpret_cast<const float4*>(s)[i];
    bf16 h0 = __float2bfloat16(v.x), h1 = __float2bfloat16(v.y);
    bf16 h2 = __float2bfloat16(v.z), h3 = __float2bfloat16(v.w);
    uint2 uh, ul;
    uh.x = packbf(__bfloat162float(h0), __bfloat162float(h1));
    uh.y = packbf(__bfloat162float(h2), __bfloat162float(h3));
    ul.x = packbf(v.x - __bfloat162float(h0), v.y - __bfloat162float(h1));
    ul.y = packbf(v.z - __bfloat162float(h2), v.w - __bfloat162float(h3));
    reinterpret_cast<uint2*>(hi)[i] = uh;
    reinterpret_cast<uint2*>(lo)[i] = ul;
}

// ---------------------------------------------------------------------------
extern "C" void kernel_launch(void* const* d_in, const int* in_sizes, int n_in,
                              void* d_out, int out_size) {
    const float* x      = (const float*)d_in[0];   // [8, 2048, 1024]
    const int*   x_mask = (const int*)d_in[1];     // [8, 2048]
    const float* W      = (const float*)d_in[2];   // [1024, 1024]
    const float* bias   = (const float*)d_in[3];   // [1024]
    float* out = (float*)d_out;                    // [8, 2048, 1024]

    cudaFuncSetAttribute(proj_gemm,   cudaFuncAttributeMaxDynamicSharedMemorySize, SMEM_PROJ);
    cudaFuncSetAttribute(scores_gemm, cudaFuncAttributeMaxDynamicSharedMemorySize, SMEM_SC);
    cudaFuncSetAttribute(av_gemm,     cudaFuncAttributeMaxDynamicSharedMemorySize, SMEM_AV);

    bf16 *wh, *wl;
    cudaGetSymbolAddress((void**)&wh, g_wh);
    cudaGetSymbolAddress((void**)&wl, g_wl);

    const int nw4 = DDIM * DDIM / 4;

    split_kernel<<<(nw4 + 255) / 256, 256>>>(W, wh, wl, nw4);
    prep_x_kernel<<<dim3(DDIM / 32, LSEQ / 32, BATCH), 256>>>(x);

    proj_gemm  <<<dim3(DDIM / 256, (BATCH * LSEQ) / 128), NTH, SMEM_PROJ>>>(bias);
    scores_gemm<<<dim3(68, BATCH), NTH, SMEM_SC>>>(x_mask);
    softmax_kernel<<<BATCH * LSEQ, 256>>>();
    av_gemm    <<<dim3(DDIM / 128, LSEQ / 128, BATCH), NTH_AV, SMEM_AV>>>(out);
}

// round 13
// speedup vs baseline: 1.2109x; 1.2109x over previous
#include <cuda_runtime.h>
#include <cuda_bf16.h>
#include <cuda_fp16.h>
#include <stdint.h>
#include <math.h>

#define BATCH 8
#define LSEQ  2048
#define DDIM  1024

typedef __nv_bfloat16 bf16;

// ---------------------------------------------------------------------------
// Scratch (device globals: no allocation allowed)
// ---------------------------------------------------------------------------
__device__ float  g_scores[(size_t)BATCH * LSEQ * LSEQ];           // 134 MB
__device__ float  g_maskv [(size_t)BATCH * LSEQ];                  // additive mask
__device__ bf16   g_xh [(size_t)BATCH * LSEQ * DDIM];
__device__ bf16   g_xl [(size_t)BATCH * LSEQ * DDIM];
__device__ __half g_xth[(size_t)BATCH * DDIM * LSEQ];              // x^T fp16 hi
__device__ bf16   g_wh [(size_t)DDIM * DDIM];
__device__ bf16   g_wl [(size_t)DDIM * DDIM];
__device__ bf16   g_ph [(size_t)BATCH * LSEQ * DDIM];
__device__ bf16   g_pl [(size_t)BATCH * LSEQ * DDIM];
__device__ __half g_ah [(size_t)BATCH * LSEQ * LSEQ];              // alpha fp16

// ---------------------------------------------------------------------------
// PTX helpers (base sm_103 target — NO tcgen05)
// ---------------------------------------------------------------------------
__device__ __forceinline__ uint32_t smem_u32(const void* p) {
    uint32_t a;
    asm("{ .reg .u64 t; cvta.to.shared.u64 t, %1; cvt.u32.u64 %0, t; }" : "=r"(a) : "l"(p));
    return a;
}

__device__ __forceinline__ void cpa16(uint32_t d, const void* s) {
    asm volatile("cp.async.cg.shared.global [%0], [%1], 16;" :: "r"(d), "l"(s) : "memory");
}

#define CP_COMMIT() asm volatile("cp.async.commit_group;" ::: "memory")
#define CP_WAIT1()  asm volatile("cp.async.wait_group 1;" ::: "memory")

#define LDSM4(r, addr) \
    asm volatile("ldmatrix.sync.aligned.m8n8.x4.shared.b16 {%0,%1,%2,%3}, [%4];" \
        : "=r"((r)[0]), "=r"((r)[1]), "=r"((r)[2]), "=r"((r)[3]) : "r"(addr))

#define MMA(d, a, b0, b1) \
    asm volatile("mma.sync.aligned.m16n8k16.row.col.f32.bf16.bf16.f32 " \
        "{%0,%1,%2,%3}, {%4,%5,%6,%7}, {%8,%9}, {%0,%1,%2,%3};" \
        : "+f"((d)[0]), "+f"((d)[1]), "+f"((d)[2]), "+f"((d)[3]) \
        : "r"((a)[0]), "r"((a)[1]), "r"((a)[2]), "r"((a)[3]), "r"(b0), "r"(b1))

#define MMAH(d, a, b0, b1) \
    asm volatile("mma.sync.aligned.m16n8k16.row.col.f32.f16.f16.f32 " \
        "{%0,%1,%2,%3}, {%4,%5,%6,%7}, {%8,%9}, {%0,%1,%2,%3};" \
        : "+f"((d)[0]), "+f"((d)[1]), "+f"((d)[2]), "+f"((d)[3]) \
        : "r"((a)[0]), "r"((a)[1]), "r"((a)[2]), "r"((a)[3]), "r"(b0), "r"(b1))

// ---------------------------------------------------------------------------
// 3-pass bf16 GEMM core (proj/scores): C(128x128) = (Ah+Al)(Bh+Bl)^T
// Stage = K=64 (64KB): A panels +0,+16384; B panels +32768,+49152.
// Panel row = 128B [hi 32k | lo 32k], XOR swizzle. 3 stages (192KB).
// 512 threads, 16 warps (4x4), warp tile 32x32. Frags double-buffered.
// ---------------------------------------------------------------------------
#define NTH 512
#define STG    65536
#define SMEM_BYTES (3 * STG)

struct Frag {
    uint32_t aH[2][4], aL[2][4], bH[2][4], bL[2][4];
};

__device__ __forceinline__ void issue_stage(uint32_t sb, int s, int tid,
    const bf16* __restrict__ Ah, const bf16* __restrict__ Al, size_t lda,
    const bf16* __restrict__ Bh, const bf16* __restrict__ Bl, size_t ldb, int kc)
{
    const uint32_t base = sb + (uint32_t)(s % 3) * STG;
    #pragma unroll
    for (int panel = 0; panel < 2; panel++) {
        const int kcp = kc + panel * 32;
        const uint32_t pb = base + (uint32_t)panel * 16384;
        #pragma unroll
        for (int j = 0; j < 2; j++) {
            const int q   = tid + j * NTH;       // 0..1023
            const int row = q >> 3;
            const int c   = q & 7;               // 0-3 hi, 4-7 lo
            const uint32_t off = (uint32_t)(row * 128) + ((uint32_t)(c ^ (row & 7)) << 4);
            const bf16* sa = (c < 4) ? Ah + (size_t)row * lda + kcp + c * 8
                                     : Al + (size_t)row * lda + kcp + (c - 4) * 8;
            const bf16* sbp = (c < 4) ? Bh + (size_t)row * ldb + kcp + c * 8
                                      : Bl + (size_t)row * ldb + kcp + (c - 4) * 8;
            cpa16(pb + off, sa);
            cpa16(pb + 32768 + off, sbp);
        }
    }
    CP_COMMIT();
}

__device__ __forceinline__ void load_frags(uint32_t stage, int kk, int m0, int n0,
                                           int lane, Frag& f)
{
    const uint32_t base = stage + (uint32_t)(kk >> 1) * 16384;
    const int cb = (kk & 1) * 2;
    const int rA = lane & 15, cA = lane >> 4;
    const int rB = (lane & 7) + ((lane >> 4) << 3), cB = (lane >> 3) & 1;
    #pragma unroll
    for (int mt = 0; mt < 2; mt++) {
        const uint32_t rowb = base + (uint32_t)((m0 + mt * 16 + rA) * 128);
        LDSM4(f.aH[mt], rowb + ((uint32_t)((cb + cA)     ^ (rA & 7)) << 4));
        LDSM4(f.aL[mt], rowb + ((uint32_t)((cb + 4 + cA) ^ (rA & 7)) << 4));
    }
    #pragma unroll
    for (int nt2 = 0; nt2 < 2; nt2++) {
        const uint32_t rowb = base + 32768 + (uint32_t)((n0 + nt2 * 16 + rB) * 128);
        LDSM4(f.bH[nt2], rowb + ((uint32_t)((cb + cB)     ^ (rB & 7)) << 4));
        LDSM4(f.bL[nt2], rowb + ((uint32_t)((cb + 4 + cB) ^ (rB & 7)) << 4));
    }
}

__device__ __forceinline__ void do_mmas(const Frag& f, float acc[2][4][4]) {
    #pragma unroll
    for (int mt = 0; mt < 2; mt++)
        #pragma unroll
        for (int nt = 0; nt < 4; nt++) {
            const int g = nt >> 1, o = (nt & 1) * 2;
            MMA(acc[mt][nt], f.aH[mt], f.bH[g][o], f.bH[g][o + 1]);
        }
    #pragma unroll
    for (int mt = 0; mt < 2; mt++)
        #pragma unroll
        for (int nt = 0; nt < 4; nt++) {
            const int g = nt >> 1, o = (nt & 1) * 2;
            MMA(acc[mt][nt], f.aH[mt], f.bL[g][o], f.bL[g][o + 1]);
        }
    #pragma unroll
    for (int mt = 0; mt < 2; mt++)
        #pragma unroll
        for (int nt = 0; nt < 4; nt++) {
            const int g = nt >> 1, o = (nt & 1) * 2;
            MMA(acc[mt][nt], f.aL[mt], f.bH[g][o], f.bH[g][o + 1]);
        }
}

// nk = K / 64, nk >= 2
__device__ __forceinline__ void run_gemm(uint32_t sb, int tid,
    const bf16* __restrict__ Ah, const bf16* __restrict__ Al, size_t lda,
    const bf16* __restrict__ Bh, const bf16* __restrict__ Bl, size_t ldb, int nk,
    float acc[2][4][4])
{
    #pragma unroll
    for (int mt = 0; mt < 2; mt++)
        #pragma unroll
        for (int nt = 0; nt < 4; nt++)
            #pragma unroll
            for (int i = 0; i < 4; i++) acc[mt][nt][i] = 0.f;

    issue_stage(sb, 0, tid, Ah, Al, lda, Bh, Bl, ldb, 0);
    issue_stage(sb, 1, tid, Ah, Al, lda, Bh, Bl, ldb, 64);

    const int wid = tid >> 5, lane = tid & 31;
    const int m0 = (wid & 3) * 32, n0 = (wid >> 2) * 32;

    CP_WAIT1();
    __syncthreads();

    Frag fa, fb;
    load_frags(sb, 0, m0, n0, lane, fa);

    for (int kt = 0; kt < nk; kt++) {
        const uint32_t cur = sb + (uint32_t)(kt % 3) * STG;
        if (kt + 2 < nk)
            issue_stage(sb, kt + 2, tid, Ah, Al, lda, Bh, Bl, ldb, (kt + 2) * 64);
        else
            CP_COMMIT();

        load_frags(cur, 1, m0, n0, lane, fb);
        do_mmas(fa, acc);
        load_frags(cur, 2, m0, n0, lane, fa);
        do_mmas(fb, acc);
        load_frags(cur, 3, m0, n0, lane, fb);
        do_mmas(fa, acc);

        CP_WAIT1();
        __syncthreads();

        const int pkt = (kt + 1 < nk) ? kt + 1 : kt;
        load_frags(sb + (uint32_t)(pkt % 3) * STG, 0, m0, n0, lane, fa);
        do_mmas(fb, acc);
    }
}

// ---------------------------------------------------------------------------
// 1-pass fp16 GEMM core (av): C(128x128) = Ah @ Bh^T.
// 256 threads, warp 64x32, K=64 stages x3 (96KB) -> 2 CTAs/SM, frag dbl-buf.
// ---------------------------------------------------------------------------
#define NTH_AV 256
#define STG_AV 32768
#define SMEM_AV (3 * STG_AV)

struct FragAv {
    uint32_t aH[4][4], bH[2][4];
};

__device__ __forceinline__ void issue_stage_av(uint32_t sb, int s, int tid,
    const __half* __restrict__ Ah, size_t lda,
    const __half* __restrict__ Bh, size_t ldb, int kc)
{
    const uint32_t base = sb + (uint32_t)(s % 3) * STG_AV;
    #pragma unroll
    for (int j = 0; j < 4; j++) {
        const int q   = tid + j * NTH_AV;
        const int row = q >> 3;
        const int c   = q & 7;
        const uint32_t off = (uint32_t)(row * 128) + ((uint32_t)(c ^ (row & 7)) << 4);
        cpa16(base + off, Ah + (size_t)row * lda + kc + c * 8);
    }
    #pragma unroll
    for (int j = 0; j < 4; j++) {
        const int q   = tid + j * NTH_AV;
        const int row = q >> 3;
        const int c   = q & 7;
        const uint32_t off = 16384u + (uint32_t)(row * 128)
                           + ((uint32_t)(c ^ (row & 7)) << 4);
        cpa16(base + off, Bh + (size_t)row * ldb + kc + c * 8);
    }
    CP_COMMIT();
}

__device__ __forceinline__ void load_frags_av(uint32_t stage, int kk, int m0, int n0,
                                              int lane, FragAv& f)
{
    const int cb = kk * 2;
    const int rA = lane & 15, cA = lane >> 4;
    const int rB = (lane & 7) + ((lane >> 4) << 3), cB = (lane >> 3) & 1;
    #pragma unroll
    for (int mt = 0; mt < 4; mt++) {
        const uint32_t rowb = stage + (uint32_t)((m0 + mt * 16 + rA) * 128);
        LDSM4(f.aH[mt], rowb + ((uint32_t)((cb + cA) ^ (rA & 7)) << 4));
    }
    #pragma unroll
    for (int nt2 = 0; nt2 < 2; nt2++) {
        const uint32_t rowb = stage + 16384 + (uint32_t)((n0 + nt2 * 16 + rB) * 128);
        LDSM4(f.bH[nt2], rowb + ((uint32_t)((cb + cB) ^ (rB & 7)) << 4));
    }
}

__device__ __forceinline__ void do_mmas_av(const FragAv& f, float acc[4][4][4]) {
    #pragma unroll
    for (int mt = 0; mt < 4; mt++)
        #pragma unroll
        for (int nt = 0; nt < 4; nt++) {
            const int g = nt >> 1, o = (nt & 1) * 2;
            MMAH(acc[mt][nt], f.aH[mt], f.bH[g][o], f.bH[g][o + 1]);
        }
}

__device__ __forceinline__ void run_gemm_av(uint32_t sb, int tid,
    const __half* __restrict__ Ah, size_t lda,
    const __half* __restrict__ Bh, size_t ldb, int nk,
    float acc[4][4][4])
{
    #pragma unroll
    for (int mt = 0; mt < 4; mt++)
        #pragma unroll
        for (int nt = 0; nt < 4; nt++)
            #pragma unroll
            for (int i = 0; i < 4; i++) acc[mt][nt][i] = 0.f;

    issue_stage_av(sb, 0, tid, Ah, lda, Bh, ldb, 0);
    issue_stage_av(sb, 1, tid, Ah, lda, Bh, ldb, 64);

    const int wid = tid >> 5, lane = tid & 31;
    const int m0 = (wid & 1) * 64, n0 = (wid >> 1) * 32;

    CP_WAIT1();
    __syncthreads();

    FragAv fa, fb;
    load_frags_av(sb, 0, m0, n0, lane, fa);

    for (int kt = 0; kt < nk; kt++) {
        const uint32_t cur = sb + (uint32_t)(kt % 3) * STG_AV;
        if (kt + 2 < nk)
            issue_stage_av(sb, kt + 2, tid, Ah, lda, Bh, ldb, (kt + 2) * 64);
        else
            CP_COMMIT();

        load_frags_av(cur, 1, m0, n0, lane, fb);
        do_mmas_av(fa, acc);
        load_frags_av(cur, 2, m0, n0, lane, fa);
        do_mmas_av(fb, acc);
        load_frags_av(cur, 3, m0, n0, lane, fb);
        do_mmas_av(fa, acc);

        CP_WAIT1();
        __syncthreads();

        const int pkt = (kt + 1 < nk) ? kt + 1 : kt;
        load_frags_av(sb + (uint32_t)(pkt % 3) * STG_AV, 0, m0, n0, lane, fa);
        do_mmas_av(fb, acc);
    }
}

__device__ __forceinline__ uint32_t packbf(float a, float b) {
    __nv_bfloat162 t = __floats2bfloat162_rn(a, b);
    return *reinterpret_cast<uint32_t*>(&t);
}
__device__ __forceinline__ uint32_t packh(float a, float b) {
    __half2 t = __floats2half2_rn(a, b);
    return *reinterpret_cast<uint32_t*>(&t);
}

// ---------------------------------------------------------------------------
// GEMM 1: proj = relu(x @ W^T + b) -> split bf16
// ---------------------------------------------------------------------------
__global__ __launch_bounds__(NTH, 1) void proj_gemm(const float* __restrict__ bias) {
    extern __shared__ char smem[];
    const uint32_t sb = smem_u32(smem);
    const int tid = threadIdx.x;
    const int mblk = blockIdx.y * 128, nblk = blockIdx.x * 128;

    float acc[2][4][4];
    run_gemm(sb, tid,
             g_xh + (size_t)mblk * DDIM, g_xl + (size_t)mblk * DDIM, DDIM,
             g_wh + (size_t)nblk * DDIM, g_wl + (size_t)nblk * DDIM, DDIM,
             DDIM / 64, acc);

    const int wid = tid >> 5, lane = tid & 31;
    const int m0 = (wid & 3) * 32, n0 = (wid >> 2) * 32;
    const int quad = lane >> 2, tq = lane & 3;

    #pragma unroll
    for (int mt = 0; mt < 2; mt++)
        #pragma unroll
        for (int nt = 0; nt < 4; nt++) {
            const int col = nblk + n0 + nt * 8 + tq * 2;
            const float b0 = bias[col], b1 = bias[col + 1];
            #pragma unroll
            for (int h = 0; h < 2; h++) {
                const int row = mblk + m0 + mt * 16 + quad + h * 8;
                float v0 = fmaxf(acc[mt][nt][h * 2 + 0] + b0, 0.f);
                float v1 = fmaxf(acc[mt][nt][h * 2 + 1] + b1, 0.f);
                bf16 h0 = __float2bfloat16(v0), h1 = __float2bfloat16(v1);
                float l0 = v0 - __bfloat162float(h0), l1 = v1 - __bfloat162float(h1);
                *reinterpret_cast<uint32_t*>(g_ph + (size_t)row * DDIM + col) =
                    packbf(__bfloat162float(h0), __bfloat162float(h1));
                *reinterpret_cast<uint32_t*>(g_pl + (size_t)row * DDIM + col) =
                    packbf(l0, l1);
            }
        }
}

// ---------------------------------------------------------------------------
// GEMM 2 (symmetric): tile pairs ti<=tj; writes RAW scores for tile + mirror
// (mask and diagonal are applied later in softmax via g_maskv).
// ---------------------------------------------------------------------------
__global__ __launch_bounds__(NTH, 1) void scores_gemm() {
    extern __shared__ char smem[];
    const uint32_t sb = smem_u32(smem);
    const int tid = threadIdx.x;
    const int b = blockIdx.y;
    int p = blockIdx.x;
    int ti = 0;
    while (p >= 16 - ti) { p -= 16 - ti; ti++; }
    const int tj = ti + p;
    const size_t pb = (size_t)b * LSEQ * DDIM;

    float acc[2][4][4];
    run_gemm(sb, tid,
             g_ph + pb + (size_t)ti * 128 * DDIM, g_pl + pb + (size_t)ti * 128 * DDIM, DDIM,
             g_ph + pb + (size_t)tj * 128 * DDIM, g_pl + pb + (size_t)tj * 128 * DDIM, DDIM,
             DDIM / 64, acc);

    __syncthreads();
    float (*sS)[129] = reinterpret_cast<float(*)[129]>(smem);

    const int wid = tid >> 5, lane = tid & 31;
    const int m0 = (wid & 3) * 32, n0 = (wid >> 2) * 32;
    const int quad = lane >> 2, tq = lane & 3;

    #pragma unroll
    for (int mt = 0; mt < 2; mt++)
        #pragma unroll
        for (int nt = 0; nt < 4; nt++) {
            const int c = n0 + nt * 8 + tq * 2;
            #pragma unroll
            for (int h = 0; h < 2; h++) {
                const int r = m0 + mt * 16 + quad + h * 8;
                sS[r][c]     = acc[mt][nt][h * 2 + 0];
                sS[r][c + 1] = acc[mt][nt][h * 2 + 1];
            }
        }
    __syncthreads();

    float* S = g_scores + (size_t)b * LSEQ * LSEQ;
    const int r  = tid & 127;
    const int c0 = (tid >> 7) * 32;

    {
        float* Srow = S + (size_t)(ti * 128 + r) * LSEQ + tj * 128;
        #pragma unroll
        for (int cc = 0; cc < 32; cc += 4) {
            const int c = c0 + cc;
            float4 v;
            v.x = sS[r][c];
            v.y = sS[r][c + 1];
            v.z = sS[r][c + 2];
            v.w = sS[r][c + 3];
            *reinterpret_cast<float4*>(Srow + c) = v;
        }
    }
    if (ti != tj) {
        float* Mrow = S + (size_t)(tj * 128 + r) * LSEQ + ti * 128;
        #pragma unroll
        for (int cc = 0; cc < 32; cc += 4) {
            const int c = c0 + cc;
            float4 v;
            v.x = sS[c][r];
            v.y = sS[c + 1][r];
            v.z = sS[c + 2][r];
            v.w = sS[c + 3][r];
            *reinterpret_cast<float4*>(Mrow + c) = v;
        }
    }
}

// ---------------------------------------------------------------------------
// GEMM 3: out = alpha @ x   (fp16 1-pass, CTA 128x128, warp 64x32, 2 CTA/SM)
// ---------------------------------------------------------------------------
__global__ __launch_bounds__(NTH_AV, 2) void av_gemm(float* __restrict__ out) {
    extern __shared__ char smem[];
    const uint32_t sb = smem_u32(smem);
    const int tid = threadIdx.x;
    const int b = blockIdx.z;
    const int mblk = blockIdx.y * 128, nblk = blockIdx.x * 128;

    float acc[4][4][4];
    run_gemm_av(sb, tid,
                g_ah + ((size_t)b * LSEQ + mblk) * LSEQ, LSEQ,
                g_xth + ((size_t)b * DDIM + nblk) * LSEQ, LSEQ,
                LSEQ / 64, acc);

    const int wid = tid >> 5, lane = tid & 31;
    const int m0 = (wid & 1) * 64, n0 = (wid >> 1) * 32;
    const int quad = lane >> 2, tq = lane & 3;

    #pragma unroll
    for (int mt = 0; mt < 4; mt++)
        #pragma unroll
        for (int nt = 0; nt < 4; nt++) {
            const int col = nblk + n0 + nt * 8 + tq * 2;
            #pragma unroll
            for (int h = 0; h < 2; h++) {
                const int row = mblk + m0 + mt * 16 + quad + h * 8;
                float2 o;
                o.x = acc[mt][nt][h * 2 + 0];
                o.y = acc[mt][nt][h * 2 + 1];
                *reinterpret_cast<float2*>(out + ((size_t)b * LSEQ + row) * DDIM + col) = o;
            }
        }
}

// ---------------------------------------------------------------------------
// Softmax over keys. Applies additive mask (g_maskv) and diagonal rule:
// v[gi] = maskv[gi] (0 if unmasked -> diag zero; -inf if masked).
// ---------------------------------------------------------------------------
__global__ __launch_bounds__(256) void softmax_kernel() {
    const size_t row = blockIdx.x;
    const int b  = (int)(row >> 11);            // row / LSEQ
    const int gi = (int)(row & (LSEQ - 1));
    const float* p  = g_scores + row * LSEQ;
    const float* mv = g_maskv + (size_t)b * LSEQ;
    const int t = threadIdx.x;

    float4 v0 = reinterpret_cast<const float4*>(p)[t * 2];
    float4 v1 = reinterpret_cast<const float4*>(p)[t * 2 + 1];
    float4 m0 = reinterpret_cast<const float4*>(mv)[t * 2];
    float4 m1 = reinterpret_cast<const float4*>(mv)[t * 2 + 1];

    float v[8];
    v[0] = v0.x + m0.x; v[1] = v0.y + m0.y; v[2] = v0.z + m0.z; v[3] = v0.w + m0.w;
    v[4] = v1.x + m1.x; v[5] = v1.y + m1.y; v[6] = v1.z + m1.z; v[7] = v1.w + m1.w;
    // diagonal: element gi of this row -> maskv[gi] (0 or -inf)
    const int base = t * 8;
    if (gi >= base && gi < base + 8) {
        const float md[8] = {m0.x, m0.y, m0.z, m0.w, m1.x, m1.y, m1.z, m1.w};
        v[gi - base] = md[gi - base];
    }

    float m = v[0];
    #pragma unroll
    for (int i = 1; i < 8; i++) m = fmaxf(m, v[i]);

    __shared__ float red[8];
    #pragma unroll
    for (int off = 16; off > 0; off >>= 1)
        m = fmaxf(m, __shfl_xor_sync(0xffffffffu, m, off));
    if ((t & 31) == 0) red[t >> 5] = m;
    __syncthreads();
    if (t == 0) {
        float mm = red[0];
        #pragma unroll
        for (int w = 1; w < 8; w++) mm = fmaxf(mm, red[w]);
        red[0] = mm;
    }
    __syncthreads();
    m = red[0];
    __syncthreads();

    float e[8];
    #pragma unroll
    for (int i = 0; i < 8; i++) e[i] = __expf(v[i] - m);
    float s = e[0] + e[1] + e[2] + e[3] + e[4] + e[5] + e[6] + e[7];
    #pragma unroll
    for (int off = 16; off > 0; off >>= 1)
        s += __shfl_xor_sync(0xffffffffu, s, off);
    if ((t & 31) == 0) red[t >> 5] = s;
    __syncthreads();
    if (t == 0) {
        float ss = 0.f;
        #pragma unroll
        for (int w = 0; w < 8; w++) ss += red[w];
        red[0] = ss;
    }
    __syncthreads();
    const float inv = 1.0f / red[0];

    uint32_t hh[4];
    #pragma unroll
    for (int i = 0; i < 4; i++)
        hh[i] = packh(e[2 * i] * inv, e[2 * i + 1] * inv);
    *reinterpret_cast<uint4*>(g_ah + row * LSEQ + t * 8) = *reinterpret_cast<uint4*>(hh);
}

// ---------------------------------------------------------------------------
// Fused x prep: read x once -> xh/xl (row-major bf16) + xth (fp16 transposed)
// ---------------------------------------------------------------------------
__global__ __launch_bounds__(256) void prep_x_kernel(const float* __restrict__ x) {
    __shared__ float t[32][33];
    const int b = blockIdx.z, d0 = blockIdx.x * 32, l0 = blockIdx.y * 32;
    const int tx = threadIdx.x & 31, ty = threadIdx.x >> 5;   // 32 x 8
    const float* xb = x + (size_t)b * LSEQ * DDIM;
    bf16* xh = g_xh + (size_t)b * LSEQ * DDIM;
    bf16* xl = g_xl + (size_t)b * LSEQ * DDIM;

    #pragma unroll
    for (int j = 0; j < 4; j++) {
        const int l = l0 + ty + j * 8;
        const float v = xb[(size_t)l * DDIM + d0 + tx];
        t[ty + j * 8][tx] = v;
        bf16 h = __float2bfloat16(v);
        xh[(size_t)l * DDIM + d0 + tx] = h;
        xl[(size_t)l * DDIM + d0 + tx] = __float2bfloat16(v - __bfloat162float(h));
    }
    __syncthreads();
    __half* oh = g_xth + (size_t)b * DDIM * LSEQ;
    #pragma unroll
    for (int j = 0; j < 4; j++) {
        float v = t[tx][ty + j * 8];
        oh[(size_t)(d0 + ty + j * 8) * LSEQ + l0 + tx] = __float2half_rn(v);
    }
}

// fp32 -> split-bf16 conversion (W)
__global__ __launch_bounds__(256) void split_kernel(const float* __restrict__ s,
                                                    bf16* __restrict__ hi,
                                                    bf16* __restrict__ lo, int n4) {
    const int i = blockIdx.x * 256 + threadIdx.x;
    if (i >= n4) return;
    float4 v = reinterpret_cast<const float4*>(s)[i];
    bf16 h0 = __float2bfloat16(v.x), h1 = __float2bfloat16(v.y);
    bf16 h2 = __float2bfloat16(v.z), h3 = __float2bfloat16(v.w);
    uint2 uh, ul;
    uh.x = packbf(__bfloat162float(h0), __bfloat162float(h1));
    uh.y = packbf(__bfloat162float(h2), __bfloat162float(h3));
    ul.x = packbf(v.x - __bfloat162float(h0), v.y - __bfloat162float(h1));
    ul.y = packbf(v.z - __bfloat162float(h2), v.w - __bfloat162float(h3));
    reinterpret_cast<uint2*>(hi)[i] = uh;
    reinterpret_cast<uint2*>(lo)[i] = ul;
}

// mask -> additive float vector (0 / -inf)
__global__ __launch_bounds__(256) void mask_kernel(const int* __restrict__ x_mask) {
    const int i = blockIdx.x * 256 + threadIdx.x;
    if (i < BATCH * LSEQ)
        g_maskv[i] = x_mask[i] ? -INFINITY : 0.f;
}

// ---------------------------------------------------------------------------
extern "C" void kernel_launch(void* const* d_in, const int* in_sizes, int n_in,
                              void* d_out, int out_size) {
    const float* x      = (const float*)d_in[0];   // [8, 2048, 1024]
    const int*   x_mask = (const int*)d_in[1];     // [8, 2048]
    const float* W      = (const float*)d_in[2];   // [1024, 1024]
    const float* bias   = (const float*)d_in[3];   // [1024]
    float* out = (float*)d_out;                    // [8, 2048, 1024]

    cudaFuncSetAttribute(proj_gemm,   cudaFuncAttributeMaxDynamicSharedMemorySize, SMEM_BYTES);
    cudaFuncSetAttribute(scores_gemm, cudaFuncAttributeMaxDynamicSharedMemorySize, SMEM_BYTES);
    cudaFuncSetAttribute(av_gemm,     cudaFuncAttributeMaxDynamicSharedMemorySize, SMEM_AV);

    bf16 *wh, *wl;
    cudaGetSymbolAddress((void**)&wh, g_wh);
    cudaGetSymbolAddress((void**)&wl, g_wl);

    const int nw4 = DDIM * DDIM / 4;

    split_kernel<<<(nw4 + 255) / 256, 256>>>(W, wh, wl, nw4);
    mask_kernel<<<(BATCH * LSEQ + 255) / 256, 256>>>(x_mask);
    prep_x_kernel<<<dim3(DDIM / 32, LSEQ / 32, BATCH), 256>>>(x);

    proj_gemm  <<<dim3(DDIM / 128, (BATCH * LSEQ) / 128), NTH, SMEM_BYTES>>>(bias);
    scores_gemm<<<dim3(136, BATCH), NTH, SMEM_BYTES>>>();
    softmax_kernel<<<BATCH * LSEQ, 256>>>();
    av_gemm    <<<dim3(DDIM / 128, LSEQ / 128, BATCH), NTH_AV, SMEM_AV>>>(out);
}